// round 1
// baseline (speedup 1.0000x reference)
#include <cuda_runtime.h>
#include <math.h>

#define NB 8
#define FH 120
#define FW 160
#define NPIX (FH*FW)
#define NSEM 16
#define NC 20
#define MS 480
#define MS2 (MS*MS)
#define TCH 18            // 0: fp_map src, 1: exp, 2..17: sem (tile); hp: 0 exp, 1..17 agent
#define VRD 100
#define CELLS (VRD*VRD)

// scratch (static device memory: allowed)
__device__ float g_hp[NB*TCH*CELLS];             // [b][c][100][100]; c0=exp count, c1..17 = agent feat 0..16
__device__ float g_tile[NB*TCH*CELLS];           // clipped agent_view tile: c0=fp_map, c1=fp_exp, c2..17=cat
__device__ float g_rot[(size_t)NB*TCH*MS2];      // rotated image (valid only inside bbox)
__device__ int   g_bbox[NB][4];                  // imin, imax, jmin, jmax (inclusive, rot-pixel space)

__global__ void k_zero() {
    int i = blockIdx.x*blockDim.x + threadIdx.x;
    if (i < NB*TCH*CELLS) g_hp[i] = 0.0f;
}

// analytic bounding box of the rotated window support (conservative)
__global__ void k_bbox(const float* __restrict__ poses) {
    int b = threadIdx.x;
    if (b >= NB) return;
    float th = (90.0f - poses[b*3+2]) * 0.017453292519943295f;
    float ct = cosf(th), st = sinf(th);
    // window footprint incl. bilinear reach, in source pixels -> normalized
    const float gxlo = 189.0f/239.5f - 1.0f, gxhi = 290.0f/239.5f - 1.0f;
    const float gylo = 239.0f/239.5f - 1.0f, gyhi = 340.0f/239.5f - 1.0f;
    float gxs[2] = {gxlo, gxhi}, gys[2] = {gylo, gyhi};
    float xmn = 1e9f, xmx = -1e9f, ymn = 1e9f, ymx = -1e9f;
    #pragma unroll
    for (int a = 0; a < 2; a++)
        #pragma unroll
        for (int c = 0; c < 2; c++) {
            float gx = gxs[a], gy = gys[c];
            // inverse of (gx,gy)=(ct*x-st*y, st*x+ct*y)
            float x =  ct*gx + st*gy;
            float y = -st*gx + ct*gy;
            xmn = fminf(xmn, x); xmx = fmaxf(xmx, x);
            ymn = fminf(ymn, y); ymx = fmaxf(ymx, y);
        }
    int jmn = (int)floorf((xmn + 1.0f)*240.0f - 0.5f) - 2;
    int jmx = (int)ceilf ((xmx + 1.0f)*240.0f - 0.5f) + 2;
    int imn = (int)floorf((ymn + 1.0f)*240.0f - 0.5f) - 2;
    int imx = (int)ceilf ((ymx + 1.0f)*240.0f - 0.5f) + 2;
    g_bbox[b][0] = max(imn, 0); g_bbox[b][1] = min(imx, MS-1);
    g_bbox[b][2] = max(jmn, 0); g_bbox[b][3] = min(jmx, MS-1);
}

// trilinear splat, pre-reduced over z into the two height sums
__global__ void k_splat(const float* __restrict__ obs, float f_cam) {
    int t = blockIdx.x*blockDim.x + threadIdx.x;
    if (t >= NB*NPIX) return;
    int b = t / NPIX, pix = t % NPIX;
    int i = pix / FW, j = pix % FW;
    const float* ob = obs + (size_t)b*NC*NPIX;

    float d = ob[3*NPIX + pix] * 100.0f;               // depth in cm (no zeros in input range)
    float X = ((float)j - 79.5f) * d / f_cam + 250.0f;
    float Z = ((float)(FH-1-i) - 59.5f) * d / f_cam + 88.0f;
    float pos0 = X / 5.0f;          // lateral  -> tile col
    float pos1 = d / 5.0f;          // forward  -> tile row
    float pos2 = Z / 5.0f + 8.0f;   // height

    float fl0 = floorf(pos0), fl1 = floorf(pos1), fl2 = floorf(pos2);
    float p0f[2] = {fl0, fl0+1.0f}, p1f[2] = {fl1, fl1+1.0f};
    float w0[2], w1[2];
    #pragma unroll
    for (int k = 0; k < 2; k++) {
        w0[k] = (1.0f - fabsf(pos0 - p0f[k])) * ((p0f[k] > 0.0f && p0f[k] < 100.0f) ? 1.0f : 0.0f);
        w1[k] = (1.0f - fabsf(pos1 - p1f[k])) * ((p1f[k] > 0.0f && p1f[k] < 100.0f) ? 1.0f : 0.0f);
    }
    float wze = 0.0f, wza = 0.0f;   // z-weight sums: exp (all safe z), agent (z in [13,25))
    #pragma unroll
    for (int k = 0; k < 2; k++) {
        float p = fl2 + (float)k;
        if (p > 0.0f && p < 80.0f) {
            float wz = 1.0f - fabsf(pos2 - p);
            wze += wz;
            int zi = (int)p;
            if (zi >= 13 && zi < 25) wza += wz;
        }
    }
    if (wze <= 0.0f && wza <= 0.0f) return;
    if (w0[0] == 0.0f && w0[1] == 0.0f) return;
    if (w1[0] == 0.0f && w1[1] == 0.0f) return;

    float sem[NSEM];
    if (wza > 0.0f) {
        #pragma unroll
        for (int s = 0; s < NSEM; s++) sem[s] = ob[(4+s)*NPIX + pix];
    }
    float* hpb = g_hp + (size_t)b*TCH*CELLS;
    #pragma unroll
    for (int a = 0; a < 2; a++) {
        if (w0[a] == 0.0f) continue;
        int ix = (int)p0f[a];
        #pragma unroll
        for (int c = 0; c < 2; c++) {
            if (w1[c] == 0.0f) continue;
            int iy = (int)p1f[c];
            float wxy = w0[a]*w1[c];
            int cell = iy*VRD + ix;
            if (wze > 0.0f) atomicAdd(hpb + cell, wxy*wze);
            if (wza > 0.0f) {
                float wag = wxy*wza;
                atomicAdd(hpb + CELLS + cell, wag);        // feat ch0 == 1
                #pragma unroll
                for (int s = 0; s < NSEM; s++)
                    atomicAdd(hpb + (size_t)(2+s)*CELLS + cell, wag*sem[s]);
            }
        }
    }
}

// build clipped compact agent_view tile
__global__ void k_tile() {
    int i = blockIdx.x*blockDim.x + threadIdx.x;
    if (i >= NB*TCH*CELLS) return;
    int c    = (i / CELLS) % TCH;
    int b    =  i / (TCH*CELLS);
    int cell =  i % CELLS;
    const float* hpb = g_hp + (size_t)b*TCH*CELLS;
    float v;
    if      (c == 0) v = fminf(hpb[CELLS + cell], 1.0f);          // fp_map = clip(agent0/1)
    else if (c == 1) v = fminf(hpb[cell], 1.0f);                  // fp_exp = clip(exp/1)
    else             v = fminf(hpb[(size_t)c*CELLS + cell] / 5.0f, 1.0f);  // cat = clip(agent_s/5)
    g_tile[i] = v;
}

// pass 1: rotation grid_sample, evaluated only inside bbox
__global__ void k_rotate(const float* __restrict__ poses) {
    int t = blockIdx.x*blockDim.x + threadIdx.x;
    if (t >= NB*MS2) return;
    int b = t / MS2;
    int r = (t % MS2) / MS, col = t % MS;
    int i0 = g_bbox[b][0], i1 = g_bbox[b][1], j0 = g_bbox[b][2], j1 = g_bbox[b][3];
    if (r < i0 || r > i1 || col < j0 || col > j1) return;

    float th = (90.0f - poses[b*3+2]) * 0.017453292519943295f;
    float ct = cosf(th), st = sinf(th);
    float x = (2.0f*col + 1.0f)/480.0f - 1.0f;
    float y = (2.0f*r   + 1.0f)/480.0f - 1.0f;
    float gx = ct*x - st*y;
    float gy = st*x + ct*y;
    float xs = (gx + 1.0f)*0.5f*479.0f;
    float ys = (gy + 1.0f)*0.5f*479.0f;
    float x0f = floorf(xs), y0f = floorf(ys);

    float acc[TCH];
    #pragma unroll
    for (int c = 0; c < TCH; c++) acc[c] = 0.0f;

    #pragma unroll
    for (int dy = 0; dy < 2; dy++) {
        float pyf = y0f + (float)dy;
        if (!(pyf >= 0.0f && pyf < 480.0f)) continue;
        int yi = (int)pyf;
        if (yi < 240 || yi >= 340) continue;             // agent_view zero outside window
        float wy = dy ? (ys - y0f) : (y0f + 1.0f - ys);
        #pragma unroll
        for (int dx = 0; dx < 2; dx++) {
            float pxf = x0f + (float)dx;
            if (!(pxf >= 0.0f && pxf < 480.0f)) continue;
            int xi = (int)pxf;
            if (xi < 190 || xi >= 290) continue;
            float wx = dx ? (xs - x0f) : (x0f + 1.0f - xs);
            float w = wx*wy;
            const float* tp = g_tile + (size_t)b*TCH*CELLS + (yi-240)*VRD + (xi-190);
            #pragma unroll
            for (int c = 0; c < TCH; c++) acc[c] += w * tp[(size_t)c*CELLS];
        }
    }
    float* rp = g_rot + (size_t)b*TCH*MS2 + (size_t)r*MS + col;
    #pragma unroll
    for (int c = 0; c < TCH; c++) rp[(size_t)c*MS2] = acc[c];
}

// pass 2: translation grid_sample + max(maps_last) + ch2/ch3 special + agent mask
__global__ void k_final(const float* __restrict__ maps_last,
                        const float* __restrict__ poses,
                        float* __restrict__ out) {
    const int GPR = MS/4;   // 120 float4 groups per row
    int t = blockIdx.x*blockDim.x + threadIdx.x;
    if (t >= NB*MS*GPR) return;
    int b    = t / (MS*GPR);
    int rem  = t % (MS*GPR);
    int r    = rem / GPR;
    int col0 = (rem % GPR)*4;

    float pxp = poses[b*3+0], pyp = poses[b*3+1];
    float stx = -((pxp*100.0f)/5.0f - 240.0f)/240.0f;
    float sty = -((pyp*100.0f)/5.0f - 240.0f)/240.0f;

    // y taps (shared by the 4 pixels)
    float yb  = (2.0f*r + 1.0f)/480.0f - 1.0f + sty;
    float ys  = (yb + 1.0f)*0.5f*479.0f;
    float y0f = floorf(ys);
    float wy0 = (y0f + 1.0f) - ys;
    float wy1 = ys - y0f;
    int   ry0 = (int)y0f, ry1 = ry0 + 1;
    int i0 = g_bbox[b][0], i1 = g_bbox[b][1], j0 = g_bbox[b][2], j1 = g_bbox[b][3];
    bool vy0 = (y0f       >= 0.0f && y0f       < 480.0f) && ry0 >= i0 && ry0 <= i1;
    bool vy1 = (y0f+1.0f  >= 0.0f && y0f+1.0f  < 480.0f) && ry1 >= i0 && ry1 <= i1;
    int ry0c = min(max(ry0,0), MS-1), ry1c = min(max(ry1,0), MS-1);

    float wx0[4], wx1[4]; int cx0[4], cx0c[4]; bool vx0[4], vx1[4];
    bool anyx = false;
    #pragma unroll
    for (int p = 0; p < 4; p++) {
        float xb  = (2.0f*(col0+p) + 1.0f)/480.0f - 1.0f + stx;
        float xs  = (xb + 1.0f)*0.5f*479.0f;
        float x0f = floorf(xs);
        wx0[p] = (x0f + 1.0f) - xs;
        wx1[p] = xs - x0f;
        cx0[p] = (int)x0f;
        vx0[p] = (x0f      >= 0.0f && x0f      < 480.0f) && cx0[p]   >= j0 && cx0[p]   <= j1;
        vx1[p] = (x0f+1.0f >= 0.0f && x0f+1.0f < 480.0f) && cx0[p]+1 >= j0 && cx0[p]+1 <= j1;
        cx0c[p] = min(max(cx0[p],0), MS-2);
        anyx = anyx || vx0[p] || vx1[p];
    }
    bool active = (vy0 || vy1) && anyx;

    int rr = (int)(pyp*100.0f/5.0f);
    int cc = (int)(pxp*100.0f/5.0f);
    bool mrow = (abs(r - rr) <= 1);

    size_t mbase = (size_t)b*NC*MS2 + (size_t)r*MS + col0;
    float4 ml3 = *(const float4*)(maps_last + mbase + 3*(size_t)MS2);

    #pragma unroll
    for (int c = 0; c < NC; c++) {
        float4 o;
        if (c == 2) {
            o = ml3;                                           // map_pred[2] = pre-mask map_pred[3] = maps_last[3]
        } else if (c == 3) {
            o = ml3;
            if (mrow) {
                if (abs(col0+0 - cc) <= 1) o.x = 1.0f;
                if (abs(col0+1 - cc) <= 1) o.y = 1.0f;
                if (abs(col0+2 - cc) <= 1) o.z = 1.0f;
                if (abs(col0+3 - cc) <= 1) o.w = 1.0f;
            }
        } else {
            float4 m = *(const float4*)(maps_last + mbase + (size_t)c*MS2);
            float tv[4] = {0.0f, 0.0f, 0.0f, 0.0f};
            if (active) {
                int rc = (c < 2) ? c : (c - 2);
                const float* base = g_rot + ((size_t)b*TCH + rc)*MS2;
                const float* row0 = base + (size_t)ry0c*MS;
                const float* row1 = base + (size_t)ry1c*MS;
                #pragma unroll
                for (int p = 0; p < 4; p++) {
                    float acc = 0.0f;
                    if (vy0) {
                        if (vx0[p]) acc += wx0[p]*wy0*row0[cx0c[p]];
                        if (vx1[p]) acc += wx1[p]*wy0*row0[cx0c[p]+1];
                    }
                    if (vy1) {
                        if (vx0[p]) acc += wx0[p]*wy1*row1[cx0c[p]];
                        if (vx1[p]) acc += wx1[p]*wy1*row1[cx0c[p]+1];
                    }
                    tv[p] = acc;
                }
            }
            o.x = fmaxf(m.x, tv[0]);
            o.y = fmaxf(m.y, tv[1]);
            o.z = fmaxf(m.z, tv[2]);
            o.w = fmaxf(m.w, tv[3]);
        }
        *(float4*)(out + mbase + (size_t)c*MS2) = o;
    }
}

extern "C" void kernel_launch(void* const* d_in, const int* in_sizes, int n_in,
                              void* d_out, int out_size) {
    const float* obs       = (const float*)d_in[0];   // (8,20,120,160)
    const float* maps_last = (const float*)d_in[1];   // (8,20,480,480)
    const float* poses     = (const float*)d_in[2];   // (8,3)
    float* out = (float*)d_out;                       // (8,20,480,480)

    float f_cam = (float)((double)FW / 2.0 / tan(79.0/2.0 * 3.14159265358979323846/180.0));

    k_zero  <<<(NB*TCH*CELLS + 255)/256, 256>>>();
    k_bbox  <<<1, NB>>>(poses);
    k_splat <<<(NB*NPIX + 255)/256, 256>>>(obs, f_cam);
    k_tile  <<<(NB*TCH*CELLS + 255)/256, 256>>>();
    k_rotate<<<(NB*MS2 + 255)/256, 256>>>(poses);
    k_final <<<(NB*MS*(MS/4) + 255)/256, 256>>>(maps_last, poses, out);
}